// round 2
// baseline (speedup 1.0000x reference)
#include <cuda_runtime.h>
#include <math.h>

#define BSZ   2
#define NSEQ  2048
#define CDIM  768
#define HH    12
#define DHD   64
#define MROWS (BSZ * NSEQ)   // 4096

typedef unsigned long long u64t;

// Scratch (device globals — allocation-free contract)
__device__ float g_Q[MROWS * CDIM];
__device__ float g_K[MROWS * CDIM];
__device__ float g_V[MROWS * CDIM];
__device__ float g_Y[MROWS * CDIM];

// ---- packed f32x2 helpers -------------------------------------------------
__device__ __forceinline__ u64t pk2(float x, float y) {
    u64t r; asm("mov.b64 %0,{%1,%2};" : "=l"(r) : "f"(x), "f"(y)); return r;
}
__device__ __forceinline__ u64t dup2(float x) { return pk2(x, x); }
__device__ __forceinline__ void unpk2(u64t v, float& x, float& y) {
    asm("mov.b64 {%0,%1},%2;" : "=f"(x), "=f"(y) : "l"(v));
}
__device__ __forceinline__ void fma2(u64t& d, u64t a, u64t b) {
    asm("fma.rn.f32x2 %0,%1,%2,%0;" : "+l"(d) : "l"(a), "l"(b));
}
__device__ __forceinline__ void mul2(u64t& d, u64t a) {
    asm("mul.rn.f32x2 %0,%0,%1;" : "+l"(d) : "l"(a));
}

// ---------------------------------------------------------------------------
// Tiled SGEMM: C[M,Nn] = A[M,K] @ Bm[K,Nn] + bias. 128x128 tile, BK=8,
// 256 threads, 8x8 per-thread microtile via f32x2 (8x4 packed accumulators).
// Double-buffered smem, one __syncthreads per K-step.
// ---------------------------------------------------------------------------
__device__ __forceinline__ void sgemm_body(
    const float* __restrict__ A,
    const float* __restrict__ Bm,
    const float* __restrict__ bias,
    float* __restrict__ Cout,
    int K, int Nn, int bm, int bn)
{
    __shared__ float As[2][8][128];
    __shared__ float Bs[2][8][128];

    const int tid = threadIdx.x;
    const int tx  = tid & 15;        // 0..15
    const int ty  = tid >> 4;        // 0..15
    const int row0 = bm * 128;
    const int col0 = bn * 128;

    const int arow = tid >> 1;       // 0..127
    const int acol = (tid & 1) * 4;  // 0 or 4
    const int brow = tid >> 5;       // 0..7
    const int bcol = (tid & 31) * 4; // 0..124

    u64t acc[8][4];
#pragma unroll
    for (int i = 0; i < 8; i++)
#pragma unroll
        for (int j = 0; j < 4; j++) acc[i][j] = 0ull;

    // Prologue: load tile 0 into buffer 0
    {
        float4 av = *(const float4*)&A[(size_t)(row0 + arow) * K + acol];
        As[0][acol + 0][arow] = av.x;
        As[0][acol + 1][arow] = av.y;
        As[0][acol + 2][arow] = av.z;
        As[0][acol + 3][arow] = av.w;
        *(float4*)&Bs[0][brow][bcol] =
            *(const float4*)&Bm[(size_t)brow * Nn + col0 + bcol];
    }
    __syncthreads();

    int s = 0;
    for (int k0 = 0; k0 < K; k0 += 8) {
        // Prefetch next tile into registers
        float4 av, bv;
        const bool has_next = (k0 + 8 < K);
        if (has_next) {
            av = *(const float4*)&A[(size_t)(row0 + arow) * K + k0 + 8 + acol];
            bv = *(const float4*)&Bm[(size_t)(k0 + 8 + brow) * Nn + col0 + bcol];
        }

#pragma unroll
        for (int kk = 0; kk < 8; kk++) {
            float a[8];
            *(float4*)(a)     = *(const float4*)&As[s][kk][ty * 8];
            *(float4*)(a + 4) = *(const float4*)&As[s][kk][ty * 8 + 4];
            ulonglong2 b0 = *(const ulonglong2*)&Bs[s][kk][tx * 8];
            ulonglong2 b1 = *(const ulonglong2*)&Bs[s][kk][tx * 8 + 4];
            u64t b[4] = {b0.x, b0.y, b1.x, b1.y};
#pragma unroll
            for (int i = 0; i < 8; i++) {
                u64t ad = dup2(a[i]);
#pragma unroll
                for (int j = 0; j < 4; j++) fma2(acc[i][j], ad, b[j]);
            }
        }

        if (has_next) {
            int ns = s ^ 1;
            As[ns][acol + 0][arow] = av.x;
            As[ns][acol + 1][arow] = av.y;
            As[ns][acol + 2][arow] = av.z;
            As[ns][acol + 3][arow] = av.w;
            *(float4*)&Bs[ns][brow][bcol] = bv;
            __syncthreads();
            s = ns;
        }
    }

    // Epilogue: add bias, store
#pragma unroll
    for (int i = 0; i < 8; i++) {
        int r = row0 + ty * 8 + i;
        int c = col0 + tx * 8;
        float4 o0, o1;
        unpk2(acc[i][0], o0.x, o0.y);
        unpk2(acc[i][1], o0.z, o0.w);
        unpk2(acc[i][2], o1.x, o1.y);
        unpk2(acc[i][3], o1.z, o1.w);
        o0.x += bias[c + 0]; o0.y += bias[c + 1];
        o0.z += bias[c + 2]; o0.w += bias[c + 3];
        o1.x += bias[c + 4]; o1.y += bias[c + 5];
        o1.z += bias[c + 6]; o1.w += bias[c + 7];
        *(float4*)&Cout[(size_t)r * Nn + c]     = o0;
        *(float4*)&Cout[(size_t)r * Nn + c + 4] = o1;
    }
}

// Fused QKV projection: blockIdx.z selects projection (0=Q,1=K,2=V)
__global__ void __launch_bounds__(256)
qkv_gemm_kernel(const float* __restrict__ x,
                const float* __restrict__ Wq, const float* __restrict__ bq,
                const float* __restrict__ Wk, const float* __restrict__ bk,
                const float* __restrict__ Wv, const float* __restrict__ bv)
{
    int p = blockIdx.z;
    const float* W = (p == 0) ? Wq : (p == 1) ? Wk : Wv;
    const float* b = (p == 0) ? bq : (p == 1) ? bk : bv;
    float* out     = (p == 0) ? g_Q : (p == 1) ? g_K : g_V;
    sgemm_body(x, W, b, out, CDIM, CDIM, blockIdx.y, blockIdx.x);
}

// Output projection: out = Y @ Wp + bp
__global__ void __launch_bounds__(256)
proj_gemm_kernel(const float* __restrict__ Wp, const float* __restrict__ bp,
                 float* __restrict__ out)
{
    sgemm_body(g_Y, Wp, bp, out, CDIM, CDIM, blockIdx.y, blockIdx.x);
}

// ---------------------------------------------------------------------------
// Flash attention: grid (NSEQ/128, HH, BSZ), 128 threads; 1 thread = 1 q row.
// q (32 x f32x2) and o (32 x f32x2) in registers; K/V streamed through smem
// in 64-row tiles; online softmax with lazy max-rescale. All FMA work packed.
// ---------------------------------------------------------------------------
__global__ void __launch_bounds__(128)
attn_kernel()
{
    const int qt = blockIdx.x;
    const int h  = blockIdx.y;
    const int b  = blockIdx.z;
    const int t  = threadIdx.x;
    const int n  = qt * 128 + t;

    __shared__ float ks[64][64];
    __shared__ float vs[64][64];

    // Load this thread's query row, pre-scaled by 1/sqrt(DH), packed f32x2
    const float scale = 0.125f;
    u64t q2[32];
    const float* qptr = &g_Q[((size_t)(b * NSEQ + n)) * CDIM + h * DHD];
#pragma unroll
    for (int d = 0; d < 64; d += 4) {
        float4 qv = *(const float4*)&qptr[d];
        q2[d / 2]     = pk2(qv.x * scale, qv.y * scale);
        q2[d / 2 + 1] = pk2(qv.z * scale, qv.w * scale);
    }

    u64t o2[32];
#pragma unroll
    for (int d = 0; d < 32; d++) o2[d] = 0ull;
    float m = -1e30f, l = 0.0f;

    for (int jt = 0; jt < NSEQ; jt += 64) {
        __syncthreads();
        // Cooperative K/V tile load: 64 rows x 64 floats each
#pragma unroll
        for (int i = 0; i < 8; i++) {
            int idx = t + i * 128;        // float4 index 0..1023
            int r   = idx >> 4;
            int d4  = (idx & 15) << 2;
            size_t base = ((size_t)(b * NSEQ + jt + r)) * CDIM + h * DHD + d4;
            *(float4*)&ks[r][d4] = *(const float4*)&g_K[base];
            *(float4*)&vs[r][d4] = *(const float4*)&g_V[base];
        }
        __syncthreads();

#pragma unroll 2
        for (int j = 0; j < 64; j++) {
            // dot(q, k_j) with 4 packed partial accumulators
            u64t sa = 0ull, sb = 0ull, sc = 0ull, sd = 0ull;
            const ulonglong2* kr = (const ulonglong2*)&ks[j][0];
#pragma unroll
            for (int d2 = 0; d2 < 16; d2 += 2) {
                ulonglong2 k0 = kr[d2];
                ulonglong2 k1 = kr[d2 + 1];
                fma2(sa, q2[2 * d2 + 0], k0.x);
                fma2(sb, q2[2 * d2 + 1], k0.y);
                fma2(sc, q2[2 * d2 + 2], k1.x);
                fma2(sd, q2[2 * d2 + 3], k1.y);
            }
            float s;
            {
                float x0, x1, x2, x3, x4, x5, x6, x7;
                unpk2(sa, x0, x1); unpk2(sb, x2, x3);
                unpk2(sc, x4, x5); unpk2(sd, x6, x7);
                s = ((x0 + x1) + (x2 + x3)) + ((x4 + x5) + (x6 + x7));
            }

            if (s > m) {   // rare rescale path (~ln(N) per row)
                u64t corr2 = dup2(__expf(m - s));
                l *= __expf(m - s);
#pragma unroll
                for (int d = 0; d < 32; d++) mul2(o2[d], corr2);
                m = s;
            }
            float p = __expf(s - m);
            l += p;
            u64t pd = dup2(p);
            const ulonglong2* vr = (const ulonglong2*)&vs[j][0];
#pragma unroll
            for (int d2 = 0; d2 < 16; d2++) {
                ulonglong2 vv = vr[d2];
                fma2(o2[2 * d2 + 0], pd, vv.x);
                fma2(o2[2 * d2 + 1], pd, vv.y);
            }
        }
    }

    const float inv = 1.0f / l;
    float* yp = &g_Y[((size_t)(b * NSEQ + n)) * CDIM + h * DHD];
#pragma unroll
    for (int d2 = 0; d2 < 32; d2 += 2) {
        float4 ov;
        unpk2(o2[d2],     ov.x, ov.y);
        unpk2(o2[d2 + 1], ov.z, ov.w);
        ov.x *= inv; ov.y *= inv; ov.z *= inv; ov.w *= inv;
        *(float4*)&yp[d2 * 2] = ov;
    }
}

// ---------------------------------------------------------------------------
extern "C" void kernel_launch(void* const* d_in, const int* in_sizes, int n_in,
                              void* d_out, int out_size)
{
    const float* x  = (const float*)d_in[0];
    const float* Wq = (const float*)d_in[1];
    const float* bq = (const float*)d_in[2];
    const float* Wk = (const float*)d_in[3];
    const float* bk = (const float*)d_in[4];
    const float* Wv = (const float*)d_in[5];
    const float* bv = (const float*)d_in[6];
    const float* Wp = (const float*)d_in[7];
    const float* bp = (const float*)d_in[8];
    float* out = (float*)d_out;

    // QKV projections (fused grid: z = projection index)
    dim3 qkv_grid(CDIM / 128, MROWS / 128, 3);
    qkv_gemm_kernel<<<qkv_grid, 256>>>(x, Wq, bq, Wk, bk, Wv, bv);

    // Flash attention
    dim3 attn_grid(NSEQ / 128, HH, BSZ);
    attn_kernel<<<attn_grid, 128>>>();

    // Output projection
    dim3 proj_grid(CDIM / 128, MROWS / 128, 1);
    proj_gemm_kernel<<<proj_grid, 256>>>(Wp, bp, out);
}